// round 16
// baseline (speedup 1.0000x reference)
#include <cuda_runtime.h>
#include <cuda_bf16.h>
#include <cstdint>
#include <cstddef>

#define DEVI static __device__ __forceinline__

constexpr int Mdim = 16384;   // B*S
constexpr int Kdim = 4096;    // INTER
constexpr int Ndim = 1024;    // HID
constexpr int BM = 128, BN = 128, BK = 64;   // BK in bf16 elements (128B rows)
constexpr int KITERS = Kdim / BK;            // 64
constexpr int ROWB = 128;                    // full cache-line rows, SW128 swizzle
constexpr int STAGE_BYTES = 2 * BM * ROWB;   // A + B per stage = 32768
constexpr int SMEM_BYTES = 2 * STAGE_BYTES;  // 65536 (2 stages)

// absmax / quant block splits
constexpr int AX_BLOCKS = 2048, AW_BLOCKS = 256;
constexpr int QX_BLOCKS = 8192, QW_BLOCKS = 1024;

// ------------------------- device scratch ----------------------------------
__device__ int g_mx_bits;    // zero-init; atomicMax idempotent across replays
__device__ int g_mw_bits;
__device__ int g_cnt[Mdim / BM];   // per-mtile completion counters (self-reset)
__device__ __align__(16) __nv_bfloat16 g_xq[(size_t)Mdim * Kdim];  // 128 MB
__device__ __align__(16) __nv_bfloat16 g_wq[(size_t)Ndim * Kdim];  // 8 MB
__device__ __align__(16) float         g_y [(size_t)Mdim * Ndim];  // 64 MB

// ------------------------- helpers -----------------------------------------
DEVI uint32_t smem_u32(const void* p) {
    uint32_t a;
    asm("{ .reg .u64 t; cvta.to.shared.u64 t, %1; cvt.u32.u64 %0, t; }" : "=r"(a) : "l"(p));
    return a;
}
DEVI void cp16(uint32_t d, const void* g) {
    asm volatile("cp.async.cg.shared.global [%0], [%1], 16;" :: "r"(d), "l"(g));
}
DEVI void cp_commit() { asm volatile("cp.async.commit_group;" ::: "memory"); }
template <int N> DEVI void cp_wait() {
    asm volatile("cp.async.wait_group %0;" :: "n"(N) : "memory");
}
DEVI void ldsm_x4(uint32_t* r, uint32_t a) {
    asm("ldmatrix.sync.aligned.m8n8.x4.shared.b16 {%0,%1,%2,%3}, [%4];"
        : "=r"(r[0]), "=r"(r[1]), "=r"(r[2]), "=r"(r[3]) : "r"(a));
}
DEVI void mma16816(float* d, const uint32_t* a, const uint32_t* b) {
    asm("mma.sync.aligned.m16n8k16.row.col.f32.bf16.bf16.f32 "
        "{%0,%1,%2,%3}, {%4,%5,%6,%7}, {%8,%9}, {%0,%1,%2,%3};"
        : "+f"(d[0]), "+f"(d[1]), "+f"(d[2]), "+f"(d[3])
        : "r"(a[0]), "r"(a[1]), "r"(a[2]), "r"(a[3]), "r"(b[0]), "r"(b[1]));
}

DEVI float qlevel(float v, float s) {
    v = fminf(fmaxf(v, -2.5f), 2.5f);
    return rintf(v * s);   // integer in [-127,127], exact in bf16
}
DEVI uint32_t packq(float a, float b, float s) {
    __nv_bfloat162 h = __floats2bfloat162_rn(qlevel(a, s), qlevel(b, s));
    return *(uint32_t*)&h;
}
// SW128 swizzle for 128B rows: byte col ^ ((row&7)<<4)
DEVI uint32_t swz(int row, uint32_t col) {
    return (uint32_t)row * 128u + (col ^ (((uint32_t)row & 7u) << 4));
}

// ------------------------- small kernels -----------------------------------
__global__ __launch_bounds__(256) void absmax_all_kernel(const float4* __restrict__ x,
                                                         const float4* __restrict__ w) {
    __shared__ float red[8];
    const bool isX = blockIdx.x < AX_BLOCKS;
    const float4* p = isX ? x : w;
    const size_t n4 = isX ? (size_t)Mdim * Kdim / 4 : (size_t)Ndim * Kdim / 4;
    const int nblk  = isX ? AX_BLOCKS : AW_BLOCKS;
    const int bid   = isX ? blockIdx.x : blockIdx.x - AX_BLOCKS;
    int* dst = isX ? &g_mx_bits : &g_mw_bits;

    float m = 0.f;
    for (size_t i = (size_t)bid * blockDim.x + threadIdx.x; i < n4;
         i += (size_t)nblk * blockDim.x) {
        float4 v = p[i];
        m = fmaxf(m, fmaxf(fmaxf(fabsf(v.x), fabsf(v.y)), fmaxf(fabsf(v.z), fabsf(v.w))));
    }
    m = fminf(m, 2.5f);
    #pragma unroll
    for (int o = 16; o; o >>= 1) m = fmaxf(m, __shfl_xor_sync(0xffffffffu, m, o));
    if ((threadIdx.x & 31) == 0) red[threadIdx.x >> 5] = m;
    __syncthreads();
    if (threadIdx.x == 0) {
        float t = red[0];
        #pragma unroll
        for (int i = 1; i < 8; i++) t = fmaxf(t, red[i]);
        atomicMax(dst, __float_as_int(t));
    }
}

__global__ __launch_bounds__(256) void quant_all_kernel(const float4* __restrict__ x,
                                                        const float4* __restrict__ w) {
    const bool isX = blockIdx.x < QX_BLOCKS;
    const float4* src = isX ? x : w;
    __nv_bfloat16* dst = isX ? g_xq : g_wq;
    const size_t n4 = isX ? (size_t)Mdim * Kdim / 4 : (size_t)Ndim * Kdim / 4;
    const int nblk  = isX ? QX_BLOCKS : QW_BLOCKS;
    const int bid   = isX ? blockIdx.x : blockIdx.x - QX_BLOCKS;
    const float s = 127.f / __int_as_float(isX ? g_mx_bits : g_mw_bits);

    for (size_t i = (size_t)bid * blockDim.x + threadIdx.x; i < n4;
         i += (size_t)nblk * blockDim.x) {
        float4 v = src[i];
        uint2 o;
        o.x = packq(v.x, v.y, s);
        o.y = packq(v.z, v.w, s);
        *(uint2*)&dst[i * 4] = o;
    }
}

// ------------------------- GEMM (bf16 HMMA, R13 loop) + fused tail LN -------
// grid (8, 128): x = N tile (W stays L2-resident), y = M tile.
__global__ __launch_bounds__(256, 2) void gemm_kernel(const float* __restrict__ input,
                                                      const float* __restrict__ bias,
                                                      const float* __restrict__ gamma,
                                                      const float* __restrict__ beta,
                                                      float* __restrict__ out) {
    extern __shared__ __align__(128) char smem[];
    const uint32_t sbase = smem_u32(smem);
    __shared__ int doLN;

    const int tid = threadIdx.x, wid = tid >> 5, lane = tid & 31;
    const int warp_m = wid >> 2, warp_n = wid & 3;          // 2 x 4 warps, 64x32 each
    const int ntile = blockIdx.x, mtile = blockIdx.y;

    const __nv_bfloat16* Ag = g_xq + (size_t)mtile * BM * Kdim;
    const __nv_bfloat16* Bg = g_wq + (size_t)ntile * BN * Kdim;

    const int ldrow = tid >> 3;                 // 32 rows per pass
    const uint32_t ldseg = (uint32_t)(tid & 7) << 4;

    float acc[4][4][4];
    #pragma unroll
    for (int i = 0; i < 4; i++)
        #pragma unroll
        for (int j = 0; j < 4; j++)
            #pragma unroll
            for (int k = 0; k < 4; k++) acc[i][j][k] = 0.f;

    auto issue = [&](int it) {
        const uint32_t sA = sbase + (it & 1) * STAGE_BYTES;
        const uint32_t sB = sA + BM * ROWB;
        const size_t koff = (size_t)it * BK;
        #pragma unroll
        for (int u = 0; u < 4; u++) {
            const int row = ldrow + u * 32;
            const uint32_t so = swz(row, ldseg);
            const size_t g = (size_t)row * Kdim + koff;
            cp16(sA + so, (const char*)(Ag + g) + ldseg);
            cp16(sB + so, (const char*)(Bg + g) + ldseg);
        }
        cp_commit();
    };

    issue(0);

    const int aR = warp_m * 64 + (lane & 15);
    const uint32_t aC = ((uint32_t)(lane >> 4)) << 4;        // 0 / 16
    const int bR = warp_n * 32 + ((lane >> 4) << 3) + (lane & 7);
    const uint32_t bC = ((uint32_t)((lane >> 3) & 1)) << 4;  // 0 / 16

    for (int it = 0; it < KITERS; ++it) {
        if (it + 1 < KITERS) { issue(it + 1); cp_wait<1>(); }
        else                 { cp_wait<0>(); }
        __syncthreads();

        const uint32_t sA = sbase + (it & 1) * STAGE_BYTES;
        const uint32_t sB = sA + BM * ROWB;

        #pragma unroll
        for (int ks = 0; ks < 4; ks++) {      // four k16 steps per 128B stage
            const uint32_t kb = (uint32_t)ks << 5;
            uint32_t afrag[4][4], bfrag[4][2];
            #pragma unroll
            for (int mi = 0; mi < 4; mi++) {
                const int r = aR + mi * 16;
                ldsm_x4(afrag[mi], sA + swz(r, kb + aC));
            }
            #pragma unroll
            for (int nj = 0; nj < 2; nj++) {
                const int r = bR + nj * 16;
                uint32_t rr[4];
                ldsm_x4(rr, sB + swz(r, kb + bC));
                bfrag[nj * 2][0]     = rr[0]; bfrag[nj * 2][1]     = rr[1];
                bfrag[nj * 2 + 1][0] = rr[2]; bfrag[nj * 2 + 1][1] = rr[3];
            }
            #pragma unroll
            for (int mi = 0; mi < 4; mi++)
                #pragma unroll
                for (int ni = 0; ni < 4; ni++)
                    mma16816(acc[mi][ni], afrag[mi], bfrag[ni]);
        }
        __syncthreads();
    }

    // epilogue: y = acc*invs + bias + residual -> g_y
    const float mx = __int_as_float(g_mx_bits);
    const float mw = __int_as_float(g_mw_bits);
    const float invs = (mx * mw) / (127.f * 127.f);
    const int gq = lane >> 2, t = lane & 3;
    #pragma unroll
    for (int mi = 0; mi < 4; mi++) {
        #pragma unroll
        for (int half = 0; half < 2; half++) {
            const int r = mtile * BM + warp_m * 64 + mi * 16 + gq + half * 8;
            #pragma unroll
            for (int ni = 0; ni < 4; ni++) {
                const int col = ntile * BN + warp_n * 32 + ni * 8 + 2 * t;
                const size_t off = (size_t)r * Ndim + col;
                float2 res;
                res.x = acc[mi][ni][half * 2 + 0] * invs + __ldg(&bias[col])     + __ldg(&input[off]);
                res.y = acc[mi][ni][half * 2 + 1] * invs + __ldg(&bias[col + 1]) + __ldg(&input[off + 1]);
                *(float2*)&g_y[off] = res;
            }
        }
    }

    // ---- fused LN: 8th finisher of this mtile normalizes its 128 rows ------
    __threadfence();                               // release g_y stores
    if (tid == 0) {
        int old = atomicAdd(&g_cnt[mtile], 1);
        doLN = (old == (Ndim / BN) - 1);
    }
    __syncthreads();
    if (doLN) {
        __threadfence();                           // acquire peers' g_y stores
        // warp-per-row: each warp handles 16 rows; lane holds 32 cols in regs
        for (int rr = wid; rr < BM; rr += 8) {
            const int row = mtile * BM + rr;
            const float* yrow = g_y + (size_t)row * Ndim;
            float4 v[8];
            float s = 0.f;
            #pragma unroll
            for (int k = 0; k < 8; k++) {
                v[k] = *(const float4*)(yrow + lane * 4 + k * 128);
                s += (v[k].x + v[k].y) + (v[k].z + v[k].w);
            }
            #pragma unroll
            for (int o = 16; o; o >>= 1) s += __shfl_xor_sync(0xffffffffu, s, o);
            const float mu = s * (1.f / Ndim);
            float sq = 0.f;
            #pragma unroll
            for (int k = 0; k < 8; k++) {
                float dx = v[k].x - mu, dy = v[k].y - mu, dz = v[k].z - mu, dw = v[k].w - mu;
                sq += (dx * dx + dy * dy) + (dz * dz + dw * dw);
            }
            #pragma unroll
            for (int o = 16; o; o >>= 1) sq += __shfl_xor_sync(0xffffffffu, sq, o);
            const float rstd = rsqrtf(sq * (1.f / Ndim) + 1e-12f);
            #pragma unroll
            for (int k = 0; k < 8; k++) {
                const int col = lane * 4 + k * 128;
                const float4 gm = *(const float4*)(gamma + col);
                const float4 bt = *(const float4*)(beta + col);
                float4 o4;
                o4.x = gm.x * (v[k].x - mu) * rstd + bt.x;
                o4.y = gm.y * (v[k].y - mu) * rstd + bt.y;
                o4.z = gm.z * (v[k].z - mu) * rstd + bt.z;
                o4.w = gm.w * (v[k].w - mu) * rstd + bt.w;
                *(float4*)(out + (size_t)row * Ndim + col) = o4;
            }
        }
        __syncthreads();
        if (tid == 0) g_cnt[mtile] = 0;            // reset for next graph replay
    }
}

// ------------------------- launch ------------------------------------------
extern "C" void kernel_launch(void* const* d_in, const int* in_sizes, int n_in,
                              void* d_out, int out_size) {
    const float* x     = (const float*)d_in[0];  // hidden_states [4,4096,4096]
    const float* inp   = (const float*)d_in[1];  // input_tensor  [4,4096,1024]
    const float* W     = (const float*)d_in[2];  // [1024,4096]
    const float* b     = (const float*)d_in[3];
    const float* gamma = (const float*)d_in[4];
    const float* beta  = (const float*)d_in[5];
    float* out = (float*)d_out;

    cudaFuncSetAttribute(gemm_kernel, cudaFuncAttributeMaxDynamicSharedMemorySize, SMEM_BYTES);

    absmax_all_kernel<<<AX_BLOCKS + AW_BLOCKS, 256>>>((const float4*)x,
                                                      (const float4*)W);       // 1
    quant_all_kernel<<<QX_BLOCKS + QW_BLOCKS, 256>>>((const float4*)x,
                                                     (const float4*)W);        // 2
    gemm_kernel<<<dim3(Ndim / BN, Mdim / BM), 256, SMEM_BYTES>>>(inp, b,
                                                                 gamma, beta, out); // 3
}

// round 17
// speedup vs baseline: 1.0424x; 1.0424x over previous
#include <cuda_runtime.h>
#include <cuda_bf16.h>
#include <cstdint>
#include <cstddef>

#define DEVI static __device__ __forceinline__

constexpr int Mdim = 16384;   // B*S
constexpr int Kdim = 4096;    // INTER
constexpr int Ndim = 1024;    // HID
constexpr int BM = 128, BN = 128, BK = 64;   // BK in bf16 elements (128B rows)
constexpr int KITERS = Kdim / BK;            // 64
constexpr int ROWB = 128;                    // full cache-line rows, SW128 swizzle
constexpr int STAGE_BYTES = 2 * BM * ROWB;   // A + B per stage = 32768
constexpr int SMEM_BYTES = 2 * STAGE_BYTES;  // 65536 (2 stages)

constexpr int NTILES = (Mdim / BM) * (Ndim / BN);  // 1024
constexpr int PERSIST_CTAS = 296;                  // 148 SMs x 2 CTAs

// absmax / quant block splits
constexpr int AX_BLOCKS = 2048, AW_BLOCKS = 256;
constexpr int QX_BLOCKS = 8192, QW_BLOCKS = 1024;

// ------------------------- device scratch ----------------------------------
__device__ int g_mx_bits;    // zero-init; atomicMax idempotent across replays
__device__ int g_mw_bits;
__device__ __align__(16) __nv_bfloat16 g_xq[(size_t)Mdim * Kdim];  // 128 MB
__device__ __align__(16) __nv_bfloat16 g_wq[(size_t)Ndim * Kdim];  // 8 MB
__device__ __align__(16) float         g_y [(size_t)Mdim * Ndim];  // 64 MB

// ------------------------- helpers -----------------------------------------
DEVI uint32_t smem_u32(const void* p) {
    uint32_t a;
    asm("{ .reg .u64 t; cvta.to.shared.u64 t, %1; cvt.u32.u64 %0, t; }" : "=r"(a) : "l"(p));
    return a;
}
DEVI void cp16(uint32_t d, const void* g) {
    asm volatile("cp.async.cg.shared.global [%0], [%1], 16;" :: "r"(d), "l"(g));
}
DEVI void cp_commit() { asm volatile("cp.async.commit_group;" ::: "memory"); }
template <int N> DEVI void cp_wait() {
    asm volatile("cp.async.wait_group %0;" :: "n"(N) : "memory");
}
DEVI void ldsm_x4(uint32_t* r, uint32_t a) {
    asm("ldmatrix.sync.aligned.m8n8.x4.shared.b16 {%0,%1,%2,%3}, [%4];"
        : "=r"(r[0]), "=r"(r[1]), "=r"(r[2]), "=r"(r[3]) : "r"(a));
}
DEVI void mma16816(float* d, const uint32_t* a, const uint32_t* b) {
    asm("mma.sync.aligned.m16n8k16.row.col.f32.bf16.bf16.f32 "
        "{%0,%1,%2,%3}, {%4,%5,%6,%7}, {%8,%9}, {%0,%1,%2,%3};"
        : "+f"(d[0]), "+f"(d[1]), "+f"(d[2]), "+f"(d[3])
        : "r"(a[0]), "r"(a[1]), "r"(a[2]), "r"(a[3]), "r"(b[0]), "r"(b[1]));
}

DEVI float qlevel(float v, float s) {
    v = fminf(fmaxf(v, -2.5f), 2.5f);
    return rintf(v * s);   // integer in [-127,127], exact in bf16
}
DEVI uint32_t packq(float a, float b, float s) {
    __nv_bfloat162 h = __floats2bfloat162_rn(qlevel(a, s), qlevel(b, s));
    return *(uint32_t*)&h;
}
// SW128 swizzle for 128B rows: byte col ^ ((row&7)<<4)
DEVI uint32_t swz(int row, uint32_t col) {
    return (uint32_t)row * 128u + (col ^ (((uint32_t)row & 7u) << 4));
}

// ------------------------- small kernels -----------------------------------
__global__ __launch_bounds__(256) void absmax_all_kernel(const float4* __restrict__ x,
                                                         const float4* __restrict__ w) {
    __shared__ float red[8];
    const bool isX = blockIdx.x < AX_BLOCKS;
    const float4* p = isX ? x : w;
    const size_t n4 = isX ? (size_t)Mdim * Kdim / 4 : (size_t)Ndim * Kdim / 4;
    const int nblk  = isX ? AX_BLOCKS : AW_BLOCKS;
    const int bid   = isX ? blockIdx.x : blockIdx.x - AX_BLOCKS;
    int* dst = isX ? &g_mx_bits : &g_mw_bits;

    float m = 0.f;
    for (size_t i = (size_t)bid * blockDim.x + threadIdx.x; i < n4;
         i += (size_t)nblk * blockDim.x) {
        float4 v = p[i];
        m = fmaxf(m, fmaxf(fmaxf(fabsf(v.x), fabsf(v.y)), fmaxf(fabsf(v.z), fabsf(v.w))));
    }
    m = fminf(m, 2.5f);
    #pragma unroll
    for (int o = 16; o; o >>= 1) m = fmaxf(m, __shfl_xor_sync(0xffffffffu, m, o));
    if ((threadIdx.x & 31) == 0) red[threadIdx.x >> 5] = m;
    __syncthreads();
    if (threadIdx.x == 0) {
        float t = red[0];
        #pragma unroll
        for (int i = 1; i < 8; i++) t = fmaxf(t, red[i]);
        atomicMax(dst, __float_as_int(t));
    }
}

__global__ __launch_bounds__(256) void quant_all_kernel(const float4* __restrict__ x,
                                                        const float4* __restrict__ w) {
    const bool isX = blockIdx.x < QX_BLOCKS;
    const float4* src = isX ? x : w;
    __nv_bfloat16* dst = isX ? g_xq : g_wq;
    const size_t n4 = isX ? (size_t)Mdim * Kdim / 4 : (size_t)Ndim * Kdim / 4;
    const int nblk  = isX ? QX_BLOCKS : QW_BLOCKS;
    const int bid   = isX ? blockIdx.x : blockIdx.x - QX_BLOCKS;
    const float s = 127.f / __int_as_float(isX ? g_mx_bits : g_mw_bits);

    for (size_t i = (size_t)bid * blockDim.x + threadIdx.x; i < n4;
         i += (size_t)nblk * blockDim.x) {
        float4 v = src[i];
        uint2 o;
        o.x = packq(v.x, v.y, s);
        o.y = packq(v.z, v.w, s);
        *(uint2*)&dst[i * 4] = o;
    }
}

// ------------------------- GEMM (bf16 HMMA, R13 loop, persistent) -----------
// 296 persistent CTAs sweep all 1024 tiles; tile = mtile*8 + ntile.
__global__ __launch_bounds__(256, 2) void gemm_kernel(const float* __restrict__ input,
                                                      const float* __restrict__ bias) {
    extern __shared__ __align__(128) char smem[];
    const uint32_t sbase = smem_u32(smem);

    const int tid = threadIdx.x, wid = tid >> 5, lane = tid & 31;
    const int warp_m = wid >> 2, warp_n = wid & 3;          // 2 x 4 warps, 64x32 each

    const int ldrow = tid >> 3;                 // 32 rows per pass
    const uint32_t ldseg = (uint32_t)(tid & 7) << 4;

    const int aR = warp_m * 64 + (lane & 15);
    const uint32_t aC = ((uint32_t)(lane >> 4)) << 4;        // 0 / 16
    const int bR = warp_n * 32 + ((lane >> 4) << 3) + (lane & 7);
    const uint32_t bC = ((uint32_t)((lane >> 3) & 1)) << 4;  // 0 / 16

    const float mx = __int_as_float(g_mx_bits);
    const float mw = __int_as_float(g_mw_bits);
    const float invs = (mx * mw) / (127.f * 127.f);
    const int gq = lane >> 2, t = lane & 3;

    for (int tile = blockIdx.x; tile < NTILES; tile += PERSIST_CTAS) {
        const int mtile = tile >> 3, ntile = tile & 7;
        const __nv_bfloat16* Ag = g_xq + (size_t)mtile * BM * Kdim;
        const __nv_bfloat16* Bg = g_wq + (size_t)ntile * BN * Kdim;

        float acc[4][4][4];
        #pragma unroll
        for (int i = 0; i < 4; i++)
            #pragma unroll
            for (int j = 0; j < 4; j++)
                #pragma unroll
                for (int k = 0; k < 4; k++) acc[i][j][k] = 0.f;

        auto issue = [&](int it) {
            const uint32_t sA = sbase + (it & 1) * STAGE_BYTES;
            const uint32_t sB = sA + BM * ROWB;
            const size_t koff = (size_t)it * BK;
            #pragma unroll
            for (int u = 0; u < 4; u++) {
                const int row = ldrow + u * 32;
                const uint32_t so = swz(row, ldseg);
                const size_t g = (size_t)row * Kdim + koff;
                cp16(sA + so, (const char*)(Ag + g) + ldseg);
                cp16(sB + so, (const char*)(Bg + g) + ldseg);
            }
            cp_commit();
        };

        issue(0);

        for (int it = 0; it < KITERS; ++it) {
            if (it + 1 < KITERS) { issue(it + 1); cp_wait<1>(); }
            else                 { cp_wait<0>(); }
            __syncthreads();

            const uint32_t sA = sbase + (it & 1) * STAGE_BYTES;
            const uint32_t sB = sA + BM * ROWB;

            #pragma unroll
            for (int ks = 0; ks < 4; ks++) {      // four k16 steps per 128B stage
                const uint32_t kb = (uint32_t)ks << 5;
                uint32_t afrag[4][4], bfrag[4][2];
                #pragma unroll
                for (int mi = 0; mi < 4; mi++) {
                    const int r = aR + mi * 16;
                    ldsm_x4(afrag[mi], sA + swz(r, kb + aC));
                }
                #pragma unroll
                for (int nj = 0; nj < 2; nj++) {
                    const int r = bR + nj * 16;
                    uint32_t rr[4];
                    ldsm_x4(rr, sB + swz(r, kb + bC));
                    bfrag[nj * 2][0]     = rr[0]; bfrag[nj * 2][1]     = rr[1];
                    bfrag[nj * 2 + 1][0] = rr[2]; bfrag[nj * 2 + 1][1] = rr[3];
                }
                #pragma unroll
                for (int mi = 0; mi < 4; mi++)
                    #pragma unroll
                    for (int ni = 0; ni < 4; ni++)
                        mma16816(acc[mi][ni], afrag[mi], bfrag[ni]);
            }
            __syncthreads();
        }

        // epilogue: y = acc*invs + bias + residual -> g_y
        #pragma unroll
        for (int mi = 0; mi < 4; mi++) {
            #pragma unroll
            for (int half = 0; half < 2; half++) {
                const int r = mtile * BM + warp_m * 64 + mi * 16 + gq + half * 8;
                #pragma unroll
                for (int ni = 0; ni < 4; ni++) {
                    const int col = ntile * BN + warp_n * 32 + ni * 8 + 2 * t;
                    const size_t off = (size_t)r * Ndim + col;
                    float2 res;
                    res.x = acc[mi][ni][half * 2 + 0] * invs + __ldg(&bias[col])     + __ldg(&input[off]);
                    res.y = acc[mi][ni][half * 2 + 1] * invs + __ldg(&bias[col + 1]) + __ldg(&input[off + 1]);
                    *(float2*)&g_y[off] = res;
                }
            }
        }
        __syncthreads();   // protect smem stages before next tile's issue(0)
    }
}

// ------------------------- LayerNorm ---------------------------------------
__global__ __launch_bounds__(256) void ln_kernel(const float* __restrict__ gamma,
                                                 const float* __restrict__ beta,
                                                 float* __restrict__ out) {
    __shared__ float red[8];
    const int row = blockIdx.x, tid = threadIdx.x;
    const float4 v = *(const float4*)&g_y[(size_t)row * Ndim + tid * 4];

    float s = v.x + v.y + v.z + v.w;
    #pragma unroll
    for (int o = 16; o; o >>= 1) s += __shfl_xor_sync(0xffffffffu, s, o);
    if ((tid & 31) == 0) red[tid >> 5] = s;
    __syncthreads();
    if (tid < 32) {
        float t = (tid < 8) ? red[tid] : 0.f;
        #pragma unroll
        for (int o = 4; o; o >>= 1) t += __shfl_xor_sync(0xffffffffu, t, o);
        if (tid == 0) red[0] = t;
    }
    __syncthreads();
    const float mu = red[0] * (1.f / Ndim);
    __syncthreads();

    const float dx = v.x - mu, dy = v.y - mu, dz = v.z - mu, dw = v.w - mu;
    float sq = dx * dx + dy * dy + dz * dz + dw * dw;
    #pragma unroll
    for (int o = 16; o; o >>= 1) sq += __shfl_xor_sync(0xffffffffu, sq, o);
    if ((tid & 31) == 0) red[tid >> 5] = sq;
    __syncthreads();
    if (tid < 32) {
        float t = (tid < 8) ? red[tid] : 0.f;
        #pragma unroll
        for (int o = 4; o; o >>= 1) t += __shfl_xor_sync(0xffffffffu, t, o);
        if (tid == 0) red[0] = t;
    }
    __syncthreads();
    const float var = red[0] * (1.f / Ndim);
    const float rstd = rsqrtf(var + 1e-12f);

    const float4 gm = *(const float4*)&gamma[tid * 4];
    const float4 bt = *(const float4*)&beta[tid * 4];
    float4 o4;
    o4.x = gm.x * dx * rstd + bt.x;
    o4.y = gm.y * dy * rstd + bt.y;
    o4.z = gm.z * dz * rstd + bt.z;
    o4.w = gm.w * dw * rstd + bt.w;
    *(float4*)&out[(size_t)row * Ndim + tid * 4] = o4;
}

// ------------------------- launch ------------------------------------------
extern "C" void kernel_launch(void* const* d_in, const int* in_sizes, int n_in,
                              void* d_out, int out_size) {
    const float* x     = (const float*)d_in[0];  // hidden_states [4,4096,4096]
    const float* inp   = (const float*)d_in[1];  // input_tensor  [4,4096,1024]
    const float* W     = (const float*)d_in[2];  // [1024,4096]
    const float* b     = (const float*)d_in[3];
    const float* gamma = (const float*)d_in[4];
    const float* beta  = (const float*)d_in[5];
    float* out = (float*)d_out;

    cudaFuncSetAttribute(gemm_kernel, cudaFuncAttributeMaxDynamicSharedMemorySize, SMEM_BYTES);

    absmax_all_kernel<<<AX_BLOCKS + AW_BLOCKS, 256>>>((const float4*)x,
                                                      (const float4*)W);       // 1
    quant_all_kernel<<<QX_BLOCKS + QW_BLOCKS, 256>>>((const float4*)x,
                                                     (const float4*)W);        // 2
    gemm_kernel<<<PERSIST_CTAS, 256, SMEM_BYTES>>>(inp, b);                    // 3
    ln_kernel<<<Mdim, 256>>>(gamma, beta, out);                                // 4
}